// round 13
// baseline (speedup 1.0000x reference)
#include <cuda_runtime.h>
#include <cuda_fp16.h>
#include <cstdint>
#include <cstddef>

// ============================================================================
// out = softmax(Q K^T / sqrt(D), axis=k) @ V,  S=8192, D=1024, fp32 in/out.
// mma.sync m16n8k16 fp16->fp32. CTA tile 128x256 with 8 warps (2Mx4N, warp
// tile 64x64), 256 threads, 1 CTA/SM: smem traffic drops to ~90 B/cyc at
// full tensor rate, below the 128 B/cyc crossbar that capped the previous
// 128x128/2-CTA config at ~78% duty. BK=64, SW128 swizzle, 3-stage cp.async,
// single mid-chunk barrier, fused softmax epilogues.
// ============================================================================

#define SQ 8192
#define DM 1024

// ---------------- scratch ---------------------------------------------------
__device__ __half g_qh[(size_t)SQ * DM];            // Q * log2e/32, fp16
__device__ __half g_kh[(size_t)SQ * DM];            // K, fp16
__device__ __half g_vt[(size_t)DM * SQ];            // V^T, fp16 [d][s]
__device__ __half g_p [(size_t)SQ * SQ];            // exp(scores), fp16
__device__ float  g_l [SQ];                         // row sums of exp

// ---------------- helpers ---------------------------------------------------
__device__ __forceinline__ uint32_t smem_u32(const void* p) {
    uint32_t a;
    asm("{ .reg .u64 t; cvta.to.shared.u64 t, %1; cvt.u32.u64 %0, t; }"
        : "=r"(a) : "l"(p));
    return a;
}

__device__ __forceinline__ float ex2(float x) {
    float y;
    asm("ex2.approx.f32 %0, %1;" : "=f"(y) : "f"(x));
    return y;
}

__device__ __forceinline__ void cp16(uint32_t d, const void* s) {
    asm volatile("cp.async.cg.shared.global [%0], [%1], 16;" :: "r"(d), "l"(s));
}
__device__ __forceinline__ void cp_commit() { asm volatile("cp.async.commit_group;"); }
template <int N> __device__ __forceinline__ void cp_wait() {
    asm volatile("cp.async.wait_group %0;" :: "n"(N));
}

__device__ __forceinline__ void ldsm4(uint32_t* r, uint32_t a) {
    asm volatile("ldmatrix.sync.aligned.m8n8.x4.shared.b16 {%0,%1,%2,%3}, [%4];"
                 : "=r"(r[0]), "=r"(r[1]), "=r"(r[2]), "=r"(r[3]) : "r"(a));
}

__device__ __forceinline__ void mma16816(float* c, const uint32_t* a,
                                         uint32_t b0, uint32_t b1) {
    asm volatile(
        "mma.sync.aligned.m16n8k16.row.col.f32.f16.f16.f32 "
        "{%0,%1,%2,%3}, {%4,%5,%6,%7}, {%8,%9}, {%0,%1,%2,%3};"
        : "+f"(c[0]), "+f"(c[1]), "+f"(c[2]), "+f"(c[3])
        : "r"(a[0]), "r"(a[1]), "r"(a[2]), "r"(a[3]), "r"(b0), "r"(b1));
}

// ---------------- GEMM: C[M,N] = A[M,K] * B[N,K]^T ---------------------------
// CTA tile 128 x 256, 8 warps 2Mx4N (warp tile 64x64), 256 threads, 1 CTA/SM.
// BK=64 halfs (128B rows, SW128 swizzle), 3-stage cp.async pipeline,
// single mid-chunk barrier, cross-chunk kk0 fragment prefetch.
#define BM 128
#define BNP 256
#define BK 64
#define NST 3
#define A_SM (BM * 128)                      // 16384 B
#define STG (A_SM + BNP * 128)               // 49152 B
#define SMEM_G (NST * STG)                   // 147456 B

template <typename T, bool EXPE, bool NORM, bool SWAPXY>
__global__ void __launch_bounds__(256, 1)
k_gemm(const __half* __restrict__ A, const __half* __restrict__ B,
       T* __restrict__ C, float* __restrict__ l,
       int lda, int ldb, int ldc, int nch) {
    constexpr int MT = 4;

    extern __shared__ __align__(1024) char smem[];
    const uint32_t sb = smem_u32(smem);
    const int tid = threadIdx.x, lane = tid & 31, wid = tid >> 5;
    const int m0 = (SWAPXY ? blockIdx.y : blockIdx.x) * BM;
    const int n0 = (SWAPXY ? blockIdx.x : blockIdx.y) * BNP;

    const __half* arow = A + (size_t)m0 * lda;
    const __half* brow = B + (size_t)n0 * ldb;

    const int c_r0 = tid >> 3;                 // cp.async row base (0..31)
    const int c_ch = tid & 7;                  // 16B chunk

    const int g = lane >> 3, lr = lane & 7;
    const int wm0 = (wid >> 2) * 64;           // 2 M-warps
    const int wn0 = (wid & 3) * 64;            // 4 N-warps
    const uint32_t alm = (uint32_t)(lr << 4);
    const uint32_t ar0 = (uint32_t)((wm0 + lr + (g & 1) * 8) * 128);
    const uint32_t axm = (uint32_t)((g >> 1) << 4) ^ alm;
    const uint32_t br0 = (uint32_t)(A_SM + (wn0 + lr + (g >> 1) * 8) * 128);
    const uint32_t bxm = (uint32_t)((g & 1) << 4) ^ alm;

    float acc[MT][8][4];
#pragma unroll
    for (int i = 0; i < MT; i++)
#pragma unroll
        for (int j = 0; j < 8; j++)
#pragma unroll
            for (int c = 0; c < 4; c++) acc[i][j][c] = 0.f;

    // ---- prologue: stages 0..NST-2 ----
#pragma unroll
    for (int j = 0; j < NST - 1; j++) {
        const uint32_t s = sb + j * STG;
        const int kc = j * BK;
#pragma unroll
        for (int it = 0; it < BM / 32; it++) {
            const int r = c_r0 + it * 32;
            cp16(s + r * 128 + ((c_ch ^ (r & 7)) << 4),
                 arow + (size_t)r * lda + kc + c_ch * 8);
        }
#pragma unroll
        for (int it = 0; it < BNP / 32; it++) {
            const int r = c_r0 + it * 32;
            cp16(s + A_SM + r * 128 + ((c_ch ^ (r & 7)) << 4),
                 brow + (size_t)r * ldb + kc + c_ch * 8);
        }
        cp_commit();
    }

    uint32_t afr[2][MT][4], bfr[2][4][4];

    // stage 0 ready + visible, preload its kk0 fragments
    cp_wait<NST - 2>();
    __syncthreads();
#pragma unroll
    for (int mt = 0; mt < MT; mt++)
        ldsm4(afr[0][mt], sb + ar0 + mt * 2048 + (0u ^ axm));
#pragma unroll
    for (int nb = 0; nb < 4; nb++)
        ldsm4(bfr[0][nb], sb + br0 + nb * 2048 + (0u ^ bxm));

    // ---- main loop over K chunks ----
    for (int i = 0; i < nch; i++) {
        const int jl = i + NST - 1;
        if (jl < nch) {
            const uint32_t s = sb + (jl % NST) * STG;
            const int kc = jl * BK;
#pragma unroll
            for (int it = 0; it < BM / 32; it++) {
                const int r = c_r0 + it * 32;
                cp16(s + r * 128 + ((c_ch ^ (r & 7)) << 4),
                     arow + (size_t)r * lda + kc + c_ch * 8);
            }
#pragma unroll
            for (int it = 0; it < BNP / 32; it++) {
                const int r = c_r0 + it * 32;
                cp16(s + A_SM + r * 128 + ((c_ch ^ (r & 7)) << 4),
                     brow + (size_t)r * ldb + kc + c_ch * 8);
            }
        }
        cp_commit();

        const uint32_t s = sb + (i % NST) * STG;

#pragma unroll
        for (int kk = 0; kk < 4; kk++) {
            if (kk < 3) {
                const uint32_t ko = (uint32_t)((kk + 1) << 5);
                const int nb_ = (kk + 1) & 1;
#pragma unroll
                for (int mt = 0; mt < MT; mt++)
                    ldsm4(afr[nb_][mt], s + ar0 + mt * 2048 + (ko ^ axm));
#pragma unroll
                for (int nb = 0; nb < 4; nb++)
                    ldsm4(bfr[nb_][nb], s + br0 + nb * 2048 + (ko ^ bxm));
            }
            if (kk == 2) {
                cp_wait<1>();        // this thread's groups <= i+1 drained
                __syncthreads();     // stage i+1 globally visible; orders
                                     // stage i-1 reads before slot reuse
            }
            const int cb = kk & 1;
#pragma unroll
            for (int mt = 0; mt < MT; mt++)
#pragma unroll
                for (int nt = 0; nt < 8; nt++)
                    mma16816(acc[mt][nt], afr[cb][mt],
                             bfr[cb][nt >> 1][(nt & 1) * 2],
                             bfr[cb][nt >> 1][(nt & 1) * 2 + 1]);
        }

        if (i + 1 < nch) {           // next-chunk kk0 prefetch (bar was at kk2)
            const uint32_t sn = sb + ((i + 1) % NST) * STG;
#pragma unroll
            for (int mt = 0; mt < MT; mt++)
                ldsm4(afr[0][mt], sn + ar0 + mt * 2048 + (0u ^ axm));
#pragma unroll
            for (int nb = 0; nb < 4; nb++)
                ldsm4(bfr[0][nb], sn + br0 + nb * 2048 + (0u ^ bxm));
        }
    }

    // ---- epilogue ----
    const int rr = lane >> 2, cc = 2 * (lane & 3);
    T* cw = C + (size_t)(m0 + wm0) * ldc + (n0 + wn0);

    float linv[MT][2];
    if constexpr (NORM) {
        float* ls = reinterpret_cast<float*>(smem);
        __syncthreads();
        if (tid < BM) ls[tid] = 1.f / l[m0 + tid];
        __syncthreads();
#pragma unroll
        for (int mt = 0; mt < MT; mt++) {
            linv[mt][0] = ls[wm0 + mt * 16 + rr];
            linv[mt][1] = ls[wm0 + mt * 16 + rr + 8];
        }
    }

#pragma unroll
    for (int mt = 0; mt < MT; mt++) {
        if constexpr (EXPE) {
            float sA = 0.f, sB = 0.f;
#pragma unroll
            for (int nt = 0; nt < 8; nt++) {
                float e0 = ex2(acc[mt][nt][0]);
                float e1 = ex2(acc[mt][nt][1]);
                float e2 = ex2(acc[mt][nt][2]);
                float e3 = ex2(acc[mt][nt][3]);
                sA += e0 + e1;
                sB += e2 + e3;
                __half2 v0 = __floats2half2_rn(e0, e1);
                __half2 v1 = __floats2half2_rn(e2, e3);
                *reinterpret_cast<__half2*>(cw + (size_t)(mt * 16 + rr) * ldc + nt * 8 + cc) = v0;
                *reinterpret_cast<__half2*>(cw + (size_t)(mt * 16 + rr + 8) * ldc + nt * 8 + cc) = v1;
            }
            sA += __shfl_xor_sync(0xFFFFFFFFu, sA, 1);
            sA += __shfl_xor_sync(0xFFFFFFFFu, sA, 2);
            sB += __shfl_xor_sync(0xFFFFFFFFu, sB, 1);
            sB += __shfl_xor_sync(0xFFFFFFFFu, sB, 2);
            if ((lane & 3) == 0) {
                atomicAdd(&l[m0 + wm0 + mt * 16 + rr], sA);
                atomicAdd(&l[m0 + wm0 + mt * 16 + rr + 8], sB);
            }
        } else if constexpr (NORM) {
#pragma unroll
            for (int nt = 0; nt < 8; nt++) {
                float2 v0 = make_float2(acc[mt][nt][0] * linv[mt][0],
                                        acc[mt][nt][1] * linv[mt][0]);
                float2 v1 = make_float2(acc[mt][nt][2] * linv[mt][1],
                                        acc[mt][nt][3] * linv[mt][1]);
                *reinterpret_cast<float2*>(cw + (size_t)(mt * 16 + rr) * ldc + nt * 8 + cc) = v0;
                *reinterpret_cast<float2*>(cw + (size_t)(mt * 16 + rr + 8) * ldc + nt * 8 + cc) = v1;
            }
        } else {
#pragma unroll
            for (int nt = 0; nt < 8; nt++) {
                float2 v0 = make_float2(acc[mt][nt][0], acc[mt][nt][1]);
                float2 v1 = make_float2(acc[mt][nt][2], acc[mt][nt][3]);
                *reinterpret_cast<float2*>(cw + (size_t)(mt * 16 + rr) * ldc + nt * 8 + cc) = v0;
                *reinterpret_cast<float2*>(cw + (size_t)(mt * 16 + rr + 8) * ldc + nt * 8 + cc) = v1;
            }
        }
    }
}

// ---------------- fused prep: zero l, cvt Q, cvt K, transpose V --------------
#define QK_BLKS (SQ * DM / 4 / 256)          // 8192
#define TR_BLKS ((DM / 32) * (SQ / 64))      // 4096

__global__ void __launch_bounds__(256)
k_prep(const float* __restrict__ q, const float* __restrict__ k,
       const float* __restrict__ v, __half* __restrict__ qh,
       __half* __restrict__ kh, __half* __restrict__ vt,
       float* __restrict__ l) {
    const int bx = blockIdx.x;
    if (bx < 2 * QK_BLKS) {
        const bool isq = bx < QK_BLKS;
        const int i = (isq ? bx : bx - QK_BLKS) * 256 + threadIdx.x;
        const float sc = isq ? 0.045084937554f : 1.0f;   // log2e/32
        float4 x = reinterpret_cast<const float4*>(isq ? q : k)[i];
        __half2* o = reinterpret_cast<__half2*>(isq ? qh : kh);
        o[2 * i]     = __floats2half2_rn(x.x * sc, x.y * sc);
        o[2 * i + 1] = __floats2half2_rn(x.z * sc, x.w * sc);
    } else if (bx < 2 * QK_BLKS + TR_BLKS) {
        __shared__ float tile[64][33];                   // [s_local][d_local]
        const int b = bx - 2 * QK_BLKS;
        const int d0 = (b % (DM / 32)) * 32, s0 = (b / (DM / 32)) * 64;
        const int tx = threadIdx.x & 31, ty = threadIdx.x >> 5;
#pragma unroll
        for (int i = 0; i < 8; i++)
            tile[ty + i * 8][tx] = v[(size_t)(s0 + ty + i * 8) * DM + d0 + tx];
        __syncthreads();
        __half2* vt2 = reinterpret_cast<__half2*>(vt);
#pragma unroll
        for (int j = 0; j < 4; j++) {
            const int dl = ty + j * 8;
            vt2[(size_t)(d0 + dl) * (SQ / 2) + s0 / 2 + tx] =
                __floats2half2_rn(tile[2 * tx][dl], tile[2 * tx + 1][dl]);
        }
    } else {
        const int i = (bx - 2 * QK_BLKS - TR_BLKS) * 256 + threadIdx.x;
        l[i] = 0.f;
    }
}

// ---------------- launcher ---------------------------------------------------
extern "C" void kernel_launch(void* const* d_in, const int* in_sizes, int n_in,
                              void* d_out, int out_size) {
    const float* q = (const float*)d_in[0];
    const float* k = (const float*)d_in[1];
    const float* v = (const float*)d_in[2];
    float* out = (float*)d_out;

    __half *qh, *kh, *vt, *p;
    float* l;
    cudaGetSymbolAddress((void**)&qh, g_qh);
    cudaGetSymbolAddress((void**)&kh, g_kh);
    cudaGetSymbolAddress((void**)&vt, g_vt);
    cudaGetSymbolAddress((void**)&p,  g_p);
    cudaGetSymbolAddress((void**)&l,  g_l);

    cudaFuncSetAttribute((void*)k_gemm<__half, true, false, false>,
                         cudaFuncAttributeMaxDynamicSharedMemorySize, SMEM_G);
    cudaFuncSetAttribute((void*)k_gemm<float, false, true, true>,
                         cudaFuncAttributeMaxDynamicSharedMemorySize, SMEM_G);

    // fused prep: cvt Q (scaled), cvt K, transpose V, zero l
    k_prep<<<2 * QK_BLKS + TR_BLKS + SQ / 256, 256>>>(q, k, v, qh, kh, vt, l);

    // P' = exp2(Qs K^T) : M=8192 x N=8192, K=1024 -> fp16, sums -> l
    k_gemm<__half, true, false, false><<<dim3(SQ / BM, SQ / BNP), 256, SMEM_G>>>(
        qh, kh, p, l, DM, DM, SQ, DM / BK);

    // out = (P' V) / l : M=8192 x N=1024, K=8192 -> fp32 (N-fast raster)
    k_gemm<float, false, true, true><<<dim3(DM / BNP, SQ / BM), 256, SMEM_G>>>(
        p, vt, out, l, SQ, SQ, DM, SQ / BK);
}